// round 16
// baseline (speedup 1.0000x reference)
#include <cuda_runtime.h>
#include <cuda_fp16.h>
#include <stdint.h>

#define Bsz 8
#define Sq 1024
#define Hdim 1024
#define NHh 16
#define HDd 64
#define NBH (Bsz * NHh)
#define NELEM (NBH * Sq * HDd)

// ---------------- device scratch ----------------
__device__ float g_q[NELEM];
__device__ float g_k[NELEM];
__device__ __half g_qh[NELEM];                // q: hi only (x0.125)
__device__ __half g_kh[NELEM];                // k: hi only
__device__ __half g_vh[NELEM];                // v: hi only
__device__ __half g_xh[Bsz * Sq * Hdim], g_xl[Bsz * Sq * Hdim];
__device__ __half g_wh[3 * Hdim * Hdim];      // W: hi only
// gate prep
__device__ float g_u[2][64];
__device__ float g_c[2];
__device__ __half g_wgh[2 * 4096];            // Wc: hi only

// ---------------- helpers ----------------
__device__ __forceinline__ uint32_t smem_u32(const void* p) {
    uint32_t a;
    asm("{ .reg .u64 t; cvta.to.shared.u64 t, %1; cvt.u32.u64 %0, t; }" : "=r"(a) : "l"(p));
    return a;
}
__device__ __forceinline__ void cp16(uint32_t dst, const void* src) {
    asm volatile("cp.async.cg.shared.global [%0], [%1], 16;" :: "r"(dst), "l"(src));
}
#define CP_COMMIT() asm volatile("cp.async.commit_group;" ::: "memory")
#define CP_WAIT(n)  asm volatile("cp.async.wait_group %0;" :: "n"(n) : "memory")

#define LDSM_X4(r0, r1, r2, r3, addr) \
    asm volatile("ldmatrix.sync.aligned.m8n8.x4.shared.b16 {%0,%1,%2,%3}, [%4];" \
        : "=r"(r0), "=r"(r1), "=r"(r2), "=r"(r3) : "r"(addr))
#define LDSM_X4_T(r0, r1, r2, r3, addr) \
    asm volatile("ldmatrix.sync.aligned.m8n8.x4.trans.shared.b16 {%0,%1,%2,%3}, [%4];" \
        : "=r"(r0), "=r"(r1), "=r"(r2), "=r"(r3) : "r"(addr))

__device__ __forceinline__ void mma16816(float& c0, float& c1, float& c2, float& c3,
                                         uint32_t a0, uint32_t a1, uint32_t a2, uint32_t a3,
                                         uint32_t b0, uint32_t b1) {
    asm volatile("mma.sync.aligned.m16n8k16.row.col.f32.f16.f16.f32 "
                 "{%0,%1,%2,%3}, {%4,%5,%6,%7}, {%8,%9}, {%0,%1,%2,%3};"
                 : "+f"(c0), "+f"(c1), "+f"(c2), "+f"(c3)
                 : "r"(a0), "r"(a1), "r"(a2), "r"(a3), "r"(b0), "r"(b1));
}
__device__ __forceinline__ void mma16816_hacc(uint32_t& c0, uint32_t& c1,
                                              uint32_t a0, uint32_t a1, uint32_t a2, uint32_t a3,
                                              uint32_t b0, uint32_t b1) {
    asm volatile("mma.sync.aligned.m16n8k16.row.col.f16.f16.f16.f16 "
                 "{%0,%1}, {%2,%3,%4,%5}, {%6,%7}, {%0,%1};"
                 : "+r"(c0), "+r"(c1)
                 : "r"(a0), "r"(a1), "r"(a2), "r"(a3), "r"(b0), "r"(b1));
}

__device__ __forceinline__ void split_pack(float x, float y, uint32_t& h, uint32_t& l) {
    __half2 hh = __floats2half2_rn(x, y);
    float rx = x - __low2float(hh);
    float ry = y - __high2float(hh);
    __half2 ll = __floats2half2_rn(rx, ry);
    h = *(uint32_t*)&hh;
    l = *(uint32_t*)&ll;
}
__device__ __forceinline__ uint32_t pack_h(float x, float y) {
    __half2 hh = __floats2half2_rn(x, y);
    return *(uint32_t*)&hh;
}

// ---------------------------------------------------------------------------
__global__ __launch_bounds__(256) void convert_x_kernel(const float* __restrict__ X)
{
    const int idx = blockIdx.x * 256 + threadIdx.x;
    float4 v = ((const float4*)X)[idx];
    uint32_t h0, l0, h1, l1;
    split_pack(v.x, v.y, h0, l0);
    split_pack(v.z, v.w, h1, l1);
    uint2 uh = {h0, h1}, ul = {l0, l1};
    *(uint2*)(g_xh + (size_t)idx * 4) = uh;
    *(uint2*)(g_xl + (size_t)idx * 4) = ul;
}

__global__ __launch_bounds__(256) void convert_w_kernel(const float* __restrict__ Wq,
                                                        const float* __restrict__ Wk,
                                                        const float* __restrict__ Wv)
{
    const float* W = blockIdx.y == 0 ? Wq : (blockIdx.y == 1 ? Wk : Wv);
    const size_t base = (size_t)blockIdx.y * Hdim * Hdim;
    const int idx = blockIdx.x * 256 + threadIdx.x;
    float4 v = ((const float4*)W)[idx];
    uint2 uh;
    uh.x = pack_h(v.x, v.y);
    uh.y = pack_h(v.z, v.w);
    *(uint2*)(g_wh + base + (size_t)idx * 4) = uh;
}

// ---------------------------------------------------------------------------
__global__ __launch_bounds__(256) void gate_prep_kernel(
    const float* __restrict__ Wcq, const float* __restrict__ bcq,
    const float* __restrict__ Wck, const float* __restrict__ bck,
    const float* __restrict__ wlqc, const float* __restrict__ wlkc)
{
    const int which = blockIdx.x;
    const float* Wc = which ? Wck : Wcq;
    const float* bc = which ? bck : bcq;
    const float* wlc = which ? wlkc : wlqc;
    __shared__ float wl_s[64];
    const int tid = threadIdx.x;
    if (tid < 64) wl_s[tid] = wlc[tid];
    __syncthreads();

    if (tid < 64) {
        float s = 0.f;
#pragma unroll
        for (int d = 0; d < 64; d++) s = fmaf(Wc[tid * 64 + d], wl_s[d], s);
        g_u[which][tid] = s;
    } else if (tid == 64) {
        float s = 0.f;
        for (int d = 0; d < 64; d++) s = fmaf(bc[d], wl_s[d], s);
        g_c[which] = s;
    }

    for (int i = tid; i < 4096; i += 256)
        g_wgh[which * 4096 + i] = __float2half_rn(Wc[i]);
}

// ---------------------------------------------------------------------------
// Q projection: CTA 128x64, 8 warps, warp 32x32.
// 2 products: Ah·Bh (f32 acc) + Al·Bh (f16 acc) -> fp32 g_q (gate needs it).
// ---------------------------------------------------------------------------
#define QKV_STAGE 20480
#define QKV_SMEM (3 * QKV_STAGE)

__global__ __launch_bounds__(256, 2) void qkv_q_kernel(const float* __restrict__ bq)
{
    extern __shared__ char smraw[];
    const uint32_t sb = smem_u32(smraw);
    const int tid = threadIdx.x, lane = tid & 31, wid = tid >> 5;
    const int wm = wid >> 1, wn = wid & 1;
    const int m0 = blockIdx.y * 128, n0 = blockIdx.x * 64;

    const __half* WH = g_wh;

    float acc[2][4][4];
    uint32_t res[2][4][2];
#pragma unroll
    for (int i = 0; i < 2; i++)
#pragma unroll
        for (int j = 0; j < 4; j++) {
#pragma unroll
            for (int r = 0; r < 4; r++) acc[i][j][r] = 0.f;
            res[i][j][0] = 0u; res[i][j][1] = 0u;
        }

    auto load_chunk = [&](int st, int c) {
        const uint32_t base = sb + st * QKV_STAGE;
        for (int i = tid; i < 512; i += 256) {
            const int r = i >> 2, u = i & 3;
            const size_t src = (size_t)(m0 + r) * Hdim + c * 32 + u * 8;
            const uint32_t rb = base + r * 128;
            cp16(rb + (((uint32_t)(u ^ (r & 7))) << 4), g_xh + src);
            cp16(rb + (((uint32_t)((u + 4) ^ (r & 7))) << 4), g_xl + src);
        }
        {
            const int k = tid >> 3, u = tid & 7;
            const uint32_t off = k * 128 + (((uint32_t)(u ^ (k & 7))) << 4);
            cp16(base + 16384 + off, WH + (size_t)(c * 32 + k) * Hdim + n0 + u * 8);
        }
    };

    load_chunk(0, 0); CP_COMMIT();
    load_chunk(1, 1); CP_COMMIT();

    int stage = 0;
    for (int c = 0; c < 32; c++) {
        CP_WAIT(1);
        __syncthreads();
        if (c + 2 < 32) {
            int st2 = stage + 2; if (st2 >= 3) st2 -= 3;
            load_chunk(st2, c + 2);
        }
        CP_COMMIT();

        const uint32_t Ast = sb + stage * QKV_STAGE;
        const uint32_t Bst = Ast + 16384;
#pragma unroll
        for (int ks = 0; ks < 2; ks++) {
            uint32_t ah[2][4], al[2][4];
#pragma unroll
            for (int mf = 0; mf < 2; mf++) {
                const int row = wm * 32 + mf * 16 + (lane & 15);
                const int ch = ks * 2 + (lane >> 4);
                const uint32_t rb = Ast + row * 128;
                LDSM_X4(ah[mf][0], ah[mf][1], ah[mf][2], ah[mf][3],
                        rb + (((uint32_t)(ch ^ (row & 7))) << 4));
                LDSM_X4(al[mf][0], al[mf][1], al[mf][2], al[mf][3],
                        rb + (((uint32_t)((ch + 4) ^ (row & 7))) << 4));
            }
            uint32_t bh[4][2];
#pragma unroll
            for (int gp = 0; gp < 2; gp++) {
                const int k = ks * 16 + (lane & 15);
                const int ch = wn * 4 + gp * 2 + (lane >> 4);
                const uint32_t bd = Bst + k * 128 + (((uint32_t)(ch ^ (k & 7))) << 4);
                LDSM_X4_T(bh[2 * gp][0], bh[2 * gp][1], bh[2 * gp + 1][0], bh[2 * gp + 1][1], bd);
            }
#pragma unroll
            for (int mf = 0; mf < 2; mf++)
#pragma unroll
                for (int nf = 0; nf < 4; nf++) {
                    mma16816(acc[mf][nf][0], acc[mf][nf][1], acc[mf][nf][2], acc[mf][nf][3],
                             ah[mf][0], ah[mf][1], ah[mf][2], ah[mf][3], bh[nf][0], bh[nf][1]);
                    mma16816_hacc(res[mf][nf][0], res[mf][nf][1],
                                  al[mf][0], al[mf][1], al[mf][2], al[mf][3], bh[nf][0], bh[nf][1]);
                }
        }
        stage = (stage == 2) ? 0 : stage + 1;
    }

#pragma unroll
    for (int nf = 0; nf < 4; nf++) {
        const int dd = wn * 32 + nf * 8 + (lane & 3) * 2;
        const int col = n0 + dd;
        const float b0 = __ldg(bq + col), b1 = __ldg(bq + col + 1);
        const int hh = n0 >> 6;
#pragma unroll
        for (int mf = 0; mf < 2; mf++) {
            const __half2 r01 = *(__half2*)&res[mf][nf][0];
            const __half2 r23 = *(__half2*)&res[mf][nf][1];
            const float rf[4] = { __low2float(r01), __high2float(r01),
                                  __low2float(r23), __high2float(r23) };
#pragma unroll
            for (int rs = 0; rs < 2; rs++) {
                const int row = m0 + wm * 32 + mf * 16 + (lane >> 2) + rs * 8;
                const int bb = row >> 10, ss = row & 1023;
                const size_t idx = ((size_t)((bb * NHh + hh) * Sq + ss)) * HDd + dd;
                float2 t;
                t.x = acc[mf][nf][rs * 2 + 0] + rf[rs * 2 + 0] + b0;
                t.y = acc[mf][nf][rs * 2 + 1] + rf[rs * 2 + 1] + b1;
                *(float2*)(g_q + idx) = t;
            }
        }
    }
}

// ---------------------------------------------------------------------------
// K/V projection: CTA 128x128, warp 32x64 (mf2 x nf8), single product.
// ---------------------------------------------------------------------------
#define KV_STAGE 24576
#define KV_SMEM (3 * KV_STAGE)

__global__ __launch_bounds__(256, 2) void qkv_kv_kernel(const float* __restrict__ bk,
                                                        const float* __restrict__ bv)
{
    extern __shared__ char smraw[];
    const uint32_t sb = smem_u32(smraw);
    const int tid = threadIdx.x, lane = tid & 31, wid = tid >> 5;
    const int wm = wid >> 1, wn = wid & 1;
    const int m0 = blockIdx.y * 128, n0 = blockIdx.x * 128, z = blockIdx.z;

    const __half* WH = g_wh + (size_t)(z + 1) * Hdim * Hdim;

    float acc[2][8][4];
#pragma unroll
    for (int i = 0; i < 2; i++)
#pragma unroll
        for (int j = 0; j < 8; j++)
#pragma unroll
            for (int r = 0; r < 4; r++) acc[i][j][r] = 0.f;

    auto load_chunk = [&](int st, int c) {
        const uint32_t base = sb + st * KV_STAGE;
        for (int i = tid; i < 512; i += 256) {
            const int r = i >> 2, u = i & 3;
            const size_t src = (size_t)(m0 + r) * Hdim + c * 32 + u * 8;
            cp16(base + r * 128 + (((uint32_t)(u ^ (r & 7))) << 4), g_xh + src);
        }
        for (int i = tid; i < 512; i += 256) {
            const int p = i >> 8, k = (i >> 3) & 31, u = i & 7;
            const uint32_t off = p * 4096 + k * 128 + (((uint32_t)(u ^ (k & 7))) << 4);
            cp16(base + 16384 + off, WH + (size_t)(c * 32 + k) * Hdim + n0 + p * 64 + u * 8);
        }
    };

    load_chunk(0, 0); CP_COMMIT();
    load_chunk(1, 1); CP_COMMIT();

    int stage = 0;
    for (int c = 0; c < 32; c++) {
        CP_WAIT(1);
        __syncthreads();
        if (c + 2 < 32) {
            int st2 = stage + 2; if (st2 >= 3) st2 -= 3;
            load_chunk(st2, c + 2);
        }
        CP_COMMIT();

        const uint32_t Ast = sb + stage * KV_STAGE;
        const uint32_t Bst = Ast + 16384 + wn * 4096;
#pragma unroll
        for (int ks = 0; ks < 2; ks++) {
            uint32_t ah[2][4];
#pragma unroll
            for (int mf = 0; mf < 2; mf++) {
                const int row = wm * 32 + mf * 16 + (lane & 15);
                const int ch = ks * 2 + (lane >> 4);
                LDSM_X4(ah[mf][0], ah[mf][1], ah[mf][2], ah[mf][3],
                        Ast + row * 128 + (((uint32_t)(ch ^ (row & 7))) << 4));
            }
            uint32_t bh[8][2];
#pragma unroll
            for (int gp = 0; gp < 4; gp++) {
                const int k = ks * 16 + (lane & 15);
                const int ch = gp * 2 + (lane >> 4);
                const uint32_t bd = Bst + k * 128 + (((uint32_t)(ch ^ (k & 7))) << 4);
                LDSM_X4_T(bh[2 * gp][0], bh[2 * gp][1], bh[2 * gp + 1][0], bh[2 * gp + 1][1], bd);
            }
#pragma unroll
            for (int mf = 0; mf < 2; mf++)
#pragma unroll
                for (int nf = 0; nf < 8; nf++)
                    mma16816(acc[mf][nf][0], acc[mf][nf][1], acc[mf][nf][2], acc[mf][nf][3],
                             ah[mf][0], ah[mf][1], ah[mf][2], ah[mf][3], bh[nf][0], bh[nf][1]);
        }
        stage = (stage == 2) ? 0 : stage + 1;
    }

    const float* bias = z ? bv : bk;
#pragma unroll
    for (int nf = 0; nf < 8; nf++) {
        const int dd = nf * 8 + (lane & 3) * 2;
        const int col = n0 + wn * 64 + dd;
        const float b0 = __ldg(bias + col), b1 = __ldg(bias + col + 1);
        const int hh = (n0 >> 6) + wn;
#pragma unroll
        for (int mf = 0; mf < 2; mf++) {
#pragma unroll
            for (int rs = 0; rs < 2; rs++) {
                const int row = m0 + wm * 32 + mf * 16 + (lane >> 2) + rs * 8;
                const int bb = row >> 10, ss = row & 1023;
                const size_t idx = ((size_t)((bb * NHh + hh) * Sq + ss)) * HDd + dd;
                const float v0 = acc[mf][nf][rs * 2 + 0] + b0;
                const float v1 = acc[mf][nf][rs * 2 + 1] + b1;
                if (z == 0) {
                    float2 t; t.x = v0; t.y = v1;
                    *(float2*)(g_k + idx) = t;
                } else {
                    *(uint32_t*)(g_vh + idx) = pack_h(v0, v1);
                }
            }
        }
    }
}

// ---------------------------------------------------------------------------
// Gate via mma.sync; both q and k outputs hi-only f16 now.
// ---------------------------------------------------------------------------
#define GT_CE 8192
#define GT_Q  43008
#define GT_SM 77824
#define GT_SMEM (77824 + 1536)
#define GPITCH 68

__global__ __launch_bounds__(256) void gate_mma_kernel(
    const float* __restrict__ cef,
    const float* __restrict__ bcq, const float* __restrict__ bck,
    const float* __restrict__ wlqq, const float* __restrict__ wlkk)
{
    extern __shared__ char smraw[];
    const uint32_t sb = smem_u32(smraw);
    const int tid = threadIdx.x, lane = tid & 31, wid = tid >> 5;
    const int which = blockIdx.y;
    const int row0 = blockIdx.x * 128;

    const float* vecs = which ? g_k : g_q;
    const float* bc   = which ? bck : bcq;
    const float* wlv  = which ? wlkk : wlqq;
    __half* oh = which ? g_kh : g_qh;
    const float oscale = which ? 1.0f : 0.125f;

    float* CEp = (float*)(smraw + GT_CE);
    float* Qp  = (float*)(smraw + GT_Q);
    float* lam_s = (float*)(smraw + GT_SM);
    float* u_s   = lam_s + 128;
    float* wlv_s = u_s + 64;
    float* bc_s  = wlv_s + 64;

    if (tid < 64) {
        u_s[tid] = g_u[which][tid];
        wlv_s[tid] = wlv[tid];
        bc_s[tid] = bc[tid];
    }

    for (int i = tid; i < 512; i += 256) {
        const int row = i >> 3, ch = i & 7;
        const uint32_t dst = sb + row * 128 + (((uint32_t)(ch ^ (row & 7))) << 4);
        cp16(dst, g_wgh + which * 4096 + row * 64 + ch * 8);
    }
    for (int i = tid; i < 2048; i += 256) {
        const int r = i >> 4, j = i & 15;
        const int R = row0 + r;
        const int b_ = R >> 14, h = (R >> 10) & 15, s = R & 1023;
        cp16(sb + GT_CE + r * 272 + j * 16,
             cef + ((size_t)((b_ << 10) + s)) * Hdim + (h << 6) + j * 4);
        cp16(sb + GT_Q + r * 272 + j * 16, vecs + (size_t)R * 64 + j * 4);
    }
    CP_COMMIT();
    CP_WAIT(0);
    __syncthreads();

    if (tid < 128) {
        const float* cer = CEp + tid * GPITCH;
        const float* qr = Qp + tid * GPITCH;
        float acc = g_c[which];
#pragma unroll
        for (int j = 0; j < 16; j++) {
            float4 c4 = *(const float4*)(cer + j * 4);
            float4 q4 = *(const float4*)(qr + j * 4);
            acc = fmaf(c4.x, u_s[j * 4 + 0], acc);
            acc = fmaf(c4.y, u_s[j * 4 + 1], acc);
            acc = fmaf(c4.z, u_s[j * 4 + 2], acc);
            acc = fmaf(c4.w, u_s[j * 4 + 3], acc);
            acc = fmaf(q4.x, wlv_s[j * 4 + 0], acc);
            acc = fmaf(q4.y, wlv_s[j * 4 + 1], acc);
            acc = fmaf(q4.z, wlv_s[j * 4 + 2], acc);
            acc = fmaf(q4.w, wlv_s[j * 4 + 3], acc);
        }
        lam_s[tid] = 1.f / (1.f + __expf(-acc));
    }
    __syncthreads();

    const int ra = wid * 16 + (lane >> 2);
    const int c2 = (lane & 3) * 2;
    float acc[8][4];
#pragma unroll
    for (int ng = 0; ng < 8; ng++)
#pragma unroll
        for (int r = 0; r < 4; r++) acc[ng][r] = 0.f;

#pragma unroll
    for (int ks = 0; ks < 4; ks++) {
        const int k0 = ks * 16 + c2;
        float2 x0 = *(float2*)(CEp + ra * GPITCH + k0);
        float2 x1 = *(float2*)(CEp + (ra + 8) * GPITCH + k0);
        float2 x2 = *(float2*)(CEp + ra * GPITCH + k0 + 8);
        float2 x3 = *(float2*)(CEp + (ra + 8) * GPITCH + k0 + 8);
        uint32_t ah0, al0, ah1, al1, ah2, al2, ah3, al3;
        split_pack(x0.x, x0.y, ah0, al0);
        split_pack(x1.x, x1.y, ah1, al1);
        split_pack(x2.x, x2.y, ah2, al2);
        split_pack(x3.x, x3.y, ah3, al3);

#pragma unroll
        for (int gp = 0; gp < 4; gp++) {
            const int k = ks * 16 + (lane & 15);
            const int ch = 2 * gp + (lane >> 4);
            const uint32_t bd = sb + k * 128 + (((uint32_t)(ch ^ (k & 7))) << 4);
            uint32_t b0, b1, b2, b3;
            LDSM_X4_T(b0, b1, b2, b3, bd);
            const int g0 = 2 * gp, g1 = 2 * gp + 1;
            mma16816(acc[g0][0], acc[g0][1], acc[g0][2], acc[g0][3],
                     ah0, ah1, ah2, ah3, b0, b1);
            mma16816(acc[g0][0], acc[g0][1], acc[g0][2], acc[g0][3],
                     al0, al1, al2, al3, b0, b1);
            mma16816(acc[g1][0], acc[g1][1], acc[g1][2], acc[g1][3],
                     ah0, ah1, ah2, ah3, b2, b3);
            mma16816(acc[g1][0], acc[g1][1], acc[g1][2], acc[g1][3],
                     al0, al1, al2, al3, b2, b3);
        }
    }

    const float lam0 = lam_s[ra];
    const float lam1 = lam_s[ra + 8];
    const int R0 = row0 + ra, R1 = R0 + 8;
#pragma unroll
    for (int ng = 0; ng < 8; ng++) {
        const int col = ng * 8 + c2;
        const float bcv0 = bc_s[col], bcv1 = bc_s[col + 1];
        float2 q0 = *(float2*)(Qp + ra * GPITCH + col);
        float2 q1 = *(float2*)(Qp + (ra + 8) * GPITCH + col);
        const float o00 = ((1.f - lam0) * q0.x + lam0 * (acc[ng][0] + bcv0)) * oscale;
        const float o01 = ((1.f - lam0) * q0.y + lam0 * (acc[ng][1] + bcv1)) * oscale;
        const float o10 = ((1.f - lam1) * q1.x + lam1 * (acc[ng][2] + bcv0)) * oscale;
        const float o11 = ((1.f - lam1) * q1.y + lam1 * (acc[ng][3] + bcv1)) * oscale;
        *(uint32_t*)(oh + (size_t)R0 * 64 + col) = pack_h(o00, o01);
        *(uint32_t*)(oh + (size_t)R1 * 64 + col) = pack_h(o10, o11);
    }
}

// ---------------------------------------------------------------------------
// Flash attention: single-product QK^T (Qh·K) and PV (Ph·V). All hi-only.
// SMEM: Q @0 (16K, becomes slot 2), slot0 @16K, slot1 @32K. 48KB, 2 CTA/SM.
// ---------------------------------------------------------------------------
#define ATT_SMEM 49152

__global__ __launch_bounds__(256, 2) void attn_mma_kernel(
    const float* __restrict__ amask, float* __restrict__ out)
{
    extern __shared__ char smraw[];
    const uint32_t sb = smem_u32(smraw);
    const int tid = threadIdx.x, lane = tid & 31, wid = tid >> 5;
    const int b_ = blockIdx.z, h = blockIdx.y, qt = blockIdx.x;

    const size_t bh_base = (size_t)(b_ * NHh + h) * Sq * HDd;
    const size_t qbase = bh_base + (size_t)qt * 128 * HDd;
    const float* mrow_b = amask + (size_t)b_ * Sq;

    auto slot_base = [&](int i) -> uint32_t {
        return (i == 2) ? sb : sb + 16384 + (uint32_t)i * 16384;
    };

    auto load_q = [&]() {
        for (int i = tid; i < 1024; i += 256) {
            const int row = i >> 3, ch = i & 7;
            const uint32_t dst = sb + row * 128 + (((uint32_t)(ch ^ (row & 7))) << 4);
            cp16(dst, g_qh + qbase + (size_t)row * 64 + ch * 8);
        }
    };
    auto load_kv = [&](uint32_t base, int kt) {
        for (int i = tid; i < 512; i += 256) {
            const int row = i >> 3, ch = i & 7;
            const uint32_t off = row * 128 + (((uint32_t)(ch ^ (row & 7))) << 4);
            const size_t src = bh_base + (size_t)(kt * 64 + row) * 64 + ch * 8;
            cp16(base + off, g_kh + src);
            cp16(base + 8192 + off, g_vh + src);
        }
    };

    load_q(); load_kv(slot_base(0), 0); CP_COMMIT();
    load_kv(slot_base(1), 1); CP_COMMIT();

    uint32_t qh[4][4];
    float o[8][4];
#pragma unroll
    for (int ng = 0; ng < 8; ng++)
#pragma unroll
        for (int r = 0; r < 4; r++) o[ng][r] = 0.f;
    float m0 = -1e30f, m1 = -1e30f, l0 = 0.f, l1 = 0.f;

    int slot = 0;
    for (int kt = 0; kt < 16; kt++) {
        CP_WAIT(1);
        __syncthreads();

        if (kt == 0) {
#pragma unroll
            for (int ks = 0; ks < 4; ks++) {
                const int row = wid * 16 + (lane & 15);
                const int ch = ks * 2 + (lane >> 4);
                const uint32_t ad = sb + row * 128 + (((uint32_t)(ch ^ (row & 7))) << 4);
                LDSM_X4(qh[ks][0], qh[ks][1], qh[ks][2], qh[ks][3], ad);
            }
            __syncthreads();
        }

        if (kt + 2 < 16) {
            int s2 = slot + 2; if (s2 >= 3) s2 -= 3;
            load_kv(slot_base(s2), kt + 2);
        }
        CP_COMMIT();

        const uint32_t Kst = slot_base(slot);
        const uint32_t Vst = Kst + 8192;

        float sv[8][4];
#pragma unroll
        for (int ng = 0; ng < 8; ng++)
#pragma unroll
            for (int r = 0; r < 4; r++) sv[ng][r] = 0.f;

#pragma unroll
        for (int ks = 0; ks < 4; ks++) {
#pragma unroll
            for (int gp = 0; gp < 4; gp++) {
                const int n = gp * 16 + (lane & 7) + 8 * ((lane >> 3) & 1);
                const int ch = ks * 2 + (lane >> 4);
                const uint32_t kd = Kst + n * 128 + (((uint32_t)(ch ^ (n & 7))) << 4);
                uint32_t k0, k1, k2, k3;
                LDSM_X4(k0, k1, k2, k3, kd);
                const int g0 = 2 * gp, g1 = 2 * gp + 1;
                mma16816(sv[g0][0], sv[g0][1], sv[g0][2], sv[g0][3],
                         qh[ks][0], qh[ks][1], qh[ks][2], qh[ks][3], k0, k2);
                mma16816(sv[g1][0], sv[g1][1], sv[g1][2], sv[g1][3],
                         qh[ks][0], qh[ks][1], qh[ks][2], qh[ks][3], k1, k3);
            }
        }

        const float* mrow = mrow_b + kt * 64;
        float rmx0 = -1e30f, rmx1 = -1e30f;
#pragma unroll
        for (int ng = 0; ng < 8; ng++) {
            const float mk0 = __ldg(mrow + ng * 8 + (lane & 3) * 2);
            const float mk1 = __ldg(mrow + ng * 8 + (lane & 3) * 2 + 1);
            sv[ng][0] += mk0; sv[ng][1] += mk1;
            sv[ng][2] += mk0; sv[ng][3] += mk1;
            rmx0 = fmaxf(rmx0, fmaxf(sv[ng][0], sv[ng][1]));
            rmx1 = fmaxf(rmx1, fmaxf(sv[ng][2], sv[ng][3]));
        }
        rmx0 = fmaxf(rmx0, __shfl_xor_sync(0xffffffffu, rmx0, 1));
        rmx0 = fmaxf(rmx0, __shfl_xor_sync(0xffffffffu, rmx0, 2));
        rmx1 = fmaxf(rmx1, __shfl_xor_sync(0xffffffffu, rmx1, 1));
        rmx1 = fmaxf(rmx1, __shfl_xor_sync(0xffffffffu, rmx1, 2));

        const float mn0 = fmaxf(m0, rmx0), mn1 = fmaxf(m1, rmx1);
        const float sc0 = __expf(m0 - mn0), sc1 = __expf(m1 - mn1);
        float rs0 = 0.f, rs1 = 0.f;
#pragma unroll
        for (int ng = 0; ng < 8; ng++) {
            sv[ng][0] = __expf(sv[ng][0] - mn0); rs0 += sv[ng][0];
            sv[ng][1] = __expf(sv[ng][1] - mn0); rs0 += sv[ng][1];
            sv[ng][2] = __expf(sv[ng][2] - mn1); rs1 += sv[ng][2];
            sv[ng][3] = __expf(sv[ng][3] - mn1); rs1 += sv[ng][3];
            o[ng][0] *= sc0; o[ng][1] *= sc0;
            o[ng][2] *= sc1; o[ng][3] *= sc1;
        }
        rs0 += __shfl_xor_sync(0xffffffffu, rs0, 1);
        rs0 += __shfl_xor_sync(0xffffffffu, rs0, 2);
        rs1 += __shfl_xor_sync(0xffffffffu, rs1, 1);
        rs1 += __shfl_xor_sync(0xffffffffu, rs1, 2);
        l0 = l0 * sc0 + rs0; l1 = l1 * sc1 + rs1;
        m0 = mn0; m1 = mn1;

#pragma unroll
        for (int ks = 0; ks < 4; ks++) {
            uint32_t ph[4];
            ph[0] = pack_h(sv[2 * ks][0], sv[2 * ks][1]);
            ph[1] = pack_h(sv[2 * ks][2], sv[2 * ks][3]);
            ph[2] = pack_h(sv[2 * ks + 1][0], sv[2 * ks + 1][1]);
            ph[3] = pack_h(sv[2 * ks + 1][2], sv[2 * ks + 1][3]);
#pragma unroll
            for (int gp = 0; gp < 4; gp++) {
                const int krow = ks * 16 + (lane & 15);
                const int ch = gp * 2 + (lane >> 4);
                const uint32_t vd = Vst + krow * 128 + (((uint32_t)(ch ^ (krow & 7))) << 4);
                uint32_t v0, v1, v2, v3;
                LDSM_X4_T(v0, v1, v2, v3, vd);
                const int g0 = 2 * gp, g1 = 2 * gp + 1;
                mma16816(o[g0][0], o[g0][1], o[g0][2], o[g0][3],
                         ph[0], ph[1], ph[2], ph[3], v0, v1);
                mma16816(o[g1][0], o[g1][1], o[g1][2], o[g1][3],
                         ph[0], ph[1], ph[2], ph[3], v2, v3);
            }
        }

        slot = (slot == 2) ? 0 : slot + 1;
    }

    const float inv0 = 1.f / l0, inv1 = 1.f / l1;
    const int r0 = qt * 128 + wid * 16 + (lane >> 2);
#pragma unroll
    for (int ng = 0; ng < 8; ng++) {
        const int col = h * 64 + ng * 8 + (lane & 3) * 2;
        float2 t0, t1;
        t0.x = o[ng][0] * inv0; t0.y = o[ng][1] * inv0;
        t1.x = o[ng][2] * inv1; t1.y = o[ng][3] * inv1;
        *(float2*)&out[(size_t)(b_ * Sq + r0) * Hdim + col] = t0;
        *(float2*)&out[(size_t)(b_ * Sq + r0 + 8) * Hdim + col] = t1;
    }
}

// ---------------------------------------------------------------------------
extern "C" void kernel_launch(void* const* d_in, const int* in_sizes, int n_in,
                              void* d_out, int out_size)
{
    const float* hs   = (const float*)d_in[0];
    const float* am   = (const float*)d_in[1];
    const float* ce   = (const float*)d_in[2];
    const float* Wq   = (const float*)d_in[3];
    const float* bq   = (const float*)d_in[4];
    const float* Wk   = (const float*)d_in[5];
    const float* bk   = (const float*)d_in[6];
    const float* Wv   = (const float*)d_in[7];
    const float* bv   = (const float*)d_in[8];
    const float* Wcq  = (const float*)d_in[9];
    const float* bcq  = (const float*)d_in[10];
    const float* Wck  = (const float*)d_in[11];
    const float* bck  = (const float*)d_in[12];
    const float* wlqc = (const float*)d_in[13];
    const float* wlqq = (const float*)d_in[14];
    const float* wlkc = (const float*)d_in[15];
    const float* wlkk = (const float*)d_in[16];
    float* out = (float*)d_out;
    (void)in_sizes; (void)n_in; (void)out_size;

    convert_x_kernel<<<(Bsz * Sq * Hdim / 4) / 256, 256>>>(hs);
    convert_w_kernel<<<dim3((Hdim * Hdim / 4) / 256, 3), 256>>>(Wq, Wk, Wv);
    gate_prep_kernel<<<2, 256>>>(Wcq, bcq, Wck, bck, wlqc, wlkc);

    cudaFuncSetAttribute(qkv_q_kernel, cudaFuncAttributeMaxDynamicSharedMemorySize, QKV_SMEM);
    qkv_q_kernel<<<dim3(16, 64), 256, QKV_SMEM>>>(bq);

    cudaFuncSetAttribute(qkv_kv_kernel, cudaFuncAttributeMaxDynamicSharedMemorySize, KV_SMEM);
    qkv_kv_kernel<<<dim3(8, 64, 2), 256, KV_SMEM>>>(bk, bv);

    cudaFuncSetAttribute(gate_mma_kernel, cudaFuncAttributeMaxDynamicSharedMemorySize, GT_SMEM);
    gate_mma_kernel<<<dim3(1024, 2), 256, GT_SMEM>>>(ce, bcq, bck, wlqq, wlkk);

    cudaFuncSetAttribute(attn_mma_kernel, cudaFuncAttributeMaxDynamicSharedMemorySize, ATT_SMEM);
    attn_mma_kernel<<<dim3(8, 16, 8), 256, ATT_SMEM>>>(am, out);
}

// round 17
// speedup vs baseline: 1.0014x; 1.0014x over previous
#include <cuda_runtime.h>
#include <cuda_fp16.h>
#include <stdint.h>

#define Bsz 8
#define Sq 1024
#define Hdim 1024
#define NHh 16
#define HDd 64
#define NBH (Bsz * NHh)
#define NELEM (NBH * Sq * HDd)

// ---------------- device scratch ----------------
__device__ float g_q[NELEM];
__device__ float g_k[NELEM];
__device__ __half g_qh[NELEM];                // q: hi only (x0.125)
__device__ __half g_kh[NELEM];                // k: hi only
__device__ __half g_vh[NELEM];                // v: hi only
__device__ __half g_xh[Bsz * Sq * Hdim], g_xl[Bsz * Sq * Hdim];
__device__ __half g_wh[3 * Hdim * Hdim];      // W: hi only
// gate prep
__device__ float g_u[2][64];
__device__ float g_c[2];
__device__ __half g_wgh[2 * 4096];            // Wc: hi only

// ---------------- helpers ----------------
__device__ __forceinline__ uint32_t smem_u32(const void* p) {
    uint32_t a;
    asm("{ .reg .u64 t; cvta.to.shared.u64 t, %1; cvt.u32.u64 %0, t; }" : "=r"(a) : "l"(p));
    return a;
}
__device__ __forceinline__ void cp16(uint32_t dst, const void* src) {
    asm volatile("cp.async.cg.shared.global [%0], [%1], 16;" :: "r"(dst), "l"(src));
}
#define CP_COMMIT() asm volatile("cp.async.commit_group;" ::: "memory")
#define CP_WAIT(n)  asm volatile("cp.async.wait_group %0;" :: "n"(n) : "memory")

#define LDSM_X4(r0, r1, r2, r3, addr) \
    asm volatile("ldmatrix.sync.aligned.m8n8.x4.shared.b16 {%0,%1,%2,%3}, [%4];" \
        : "=r"(r0), "=r"(r1), "=r"(r2), "=r"(r3) : "r"(addr))
#define LDSM_X4_T(r0, r1, r2, r3, addr) \
    asm volatile("ldmatrix.sync.aligned.m8n8.x4.trans.shared.b16 {%0,%1,%2,%3}, [%4];" \
        : "=r"(r0), "=r"(r1), "=r"(r2), "=r"(r3) : "r"(addr))

__device__ __forceinline__ void mma16816(float& c0, float& c1, float& c2, float& c3,
                                         uint32_t a0, uint32_t a1, uint32_t a2, uint32_t a3,
                                         uint32_t b0, uint32_t b1) {
    asm volatile("mma.sync.aligned.m16n8k16.row.col.f32.f16.f16.f32 "
                 "{%0,%1,%2,%3}, {%4,%5,%6,%7}, {%8,%9}, {%0,%1,%2,%3};"
                 : "+f"(c0), "+f"(c1), "+f"(c2), "+f"(c3)
                 : "r"(a0), "r"(a1), "r"(a2), "r"(a3), "r"(b0), "r"(b1));
}
__device__ __forceinline__ void mma16816_hacc(uint32_t& c0, uint32_t& c1,
                                              uint32_t a0, uint32_t a1, uint32_t a2, uint32_t a3,
                                              uint32_t b0, uint32_t b1) {
    asm volatile("mma.sync.aligned.m16n8k16.row.col.f16.f16.f16.f16 "
                 "{%0,%1}, {%2,%3,%4,%5}, {%6,%7}, {%0,%1};"
                 : "+r"(c0), "+r"(c1)
                 : "r"(a0), "r"(a1), "r"(a2), "r"(a3), "r"(b0), "r"(b1));
}

__device__ __forceinline__ void split_pack(float x, float y, uint32_t& h, uint32_t& l) {
    __half2 hh = __floats2half2_rn(x, y);
    float rx = x - __low2float(hh);
    float ry = y - __high2float(hh);
    __half2 ll = __floats2half2_rn(rx, ry);
    h = *(uint32_t*)&hh;
    l = *(uint32_t*)&ll;
}
__device__ __forceinline__ uint32_t pack_h(float x, float y) {
    __half2 hh = __floats2half2_rn(x, y);
    return *(uint32_t*)&hh;
}

// ---------------------------------------------------------------------------
__global__ __launch_bounds__(256) void convert_x_kernel(const float* __restrict__ X)
{
    const int idx = blockIdx.x * 256 + threadIdx.x;
    float4 v = ((const float4*)X)[idx];
    uint32_t h0, l0, h1, l1;
    split_pack(v.x, v.y, h0, l0);
    split_pack(v.z, v.w, h1, l1);
    uint2 uh = {h0, h1}, ul = {l0, l1};
    *(uint2*)(g_xh + (size_t)idx * 4) = uh;
    *(uint2*)(g_xl + (size_t)idx * 4) = ul;
}

__global__ __launch_bounds__(256) void convert_w_kernel(const float* __restrict__ Wq,
                                                        const float* __restrict__ Wk,
                                                        const float* __restrict__ Wv)
{
    const float* W = blockIdx.y == 0 ? Wq : (blockIdx.y == 1 ? Wk : Wv);
    const size_t base = (size_t)blockIdx.y * Hdim * Hdim;
    const int idx = blockIdx.x * 256 + threadIdx.x;
    float4 v = ((const float4*)W)[idx];
    uint2 uh;
    uh.x = pack_h(v.x, v.y);
    uh.y = pack_h(v.z, v.w);
    *(uint2*)(g_wh + base + (size_t)idx * 4) = uh;
}

// ---------------------------------------------------------------------------
__global__ __launch_bounds__(256) void gate_prep_kernel(
    const float* __restrict__ Wcq, const float* __restrict__ bcq,
    const float* __restrict__ Wck, const float* __restrict__ bck,
    const float* __restrict__ wlqc, const float* __restrict__ wlkc)
{
    const int which = blockIdx.x;
    const float* Wc = which ? Wck : Wcq;
    const float* bc = which ? bck : bcq;
    const float* wlc = which ? wlkc : wlqc;
    __shared__ float wl_s[64];
    const int tid = threadIdx.x;
    if (tid < 64) wl_s[tid] = wlc[tid];
    __syncthreads();

    if (tid < 64) {
        float s = 0.f;
#pragma unroll
        for (int d = 0; d < 64; d++) s = fmaf(Wc[tid * 64 + d], wl_s[d], s);
        g_u[which][tid] = s;
    } else if (tid == 64) {
        float s = 0.f;
        for (int d = 0; d < 64; d++) s = fmaf(bc[d], wl_s[d], s);
        g_c[which] = s;
    }

    for (int i = tid; i < 4096; i += 256)
        g_wgh[which * 4096 + i] = __float2half_rn(Wc[i]);
}

// ---------------------------------------------------------------------------
// Q projection: CTA 128x64, 8 warps, warp 32x32.
// 2 products: Ah·Bh (f32 acc) + Al·Bh (f16 acc) -> fp32 g_q (gate needs it).
// ---------------------------------------------------------------------------
#define QKV_STAGE 20480
#define QKV_SMEM (3 * QKV_STAGE)

__global__ __launch_bounds__(256, 2) void qkv_q_kernel(const float* __restrict__ bq)
{
    extern __shared__ char smraw[];
    const uint32_t sb = smem_u32(smraw);
    const int tid = threadIdx.x, lane = tid & 31, wid = tid >> 5;
    const int wm = wid >> 1, wn = wid & 1;
    const int m0 = blockIdx.y * 128, n0 = blockIdx.x * 64;

    const __half* WH = g_wh;

    float acc[2][4][4];
    uint32_t res[2][4][2];
#pragma unroll
    for (int i = 0; i < 2; i++)
#pragma unroll
        for (int j = 0; j < 4; j++) {
#pragma unroll
            for (int r = 0; r < 4; r++) acc[i][j][r] = 0.f;
            res[i][j][0] = 0u; res[i][j][1] = 0u;
        }

    auto load_chunk = [&](int st, int c) {
        const uint32_t base = sb + st * QKV_STAGE;
        for (int i = tid; i < 512; i += 256) {
            const int r = i >> 2, u = i & 3;
            const size_t src = (size_t)(m0 + r) * Hdim + c * 32 + u * 8;
            const uint32_t rb = base + r * 128;
            cp16(rb + (((uint32_t)(u ^ (r & 7))) << 4), g_xh + src);
            cp16(rb + (((uint32_t)((u + 4) ^ (r & 7))) << 4), g_xl + src);
        }
        {
            const int k = tid >> 3, u = tid & 7;
            const uint32_t off = k * 128 + (((uint32_t)(u ^ (k & 7))) << 4);
            cp16(base + 16384 + off, WH + (size_t)(c * 32 + k) * Hdim + n0 + u * 8);
        }
    };

    load_chunk(0, 0); CP_COMMIT();
    load_chunk(1, 1); CP_COMMIT();

    int stage = 0;
    for (int c = 0; c < 32; c++) {
        CP_WAIT(1);
        __syncthreads();
        if (c + 2 < 32) {
            int st2 = stage + 2; if (st2 >= 3) st2 -= 3;
            load_chunk(st2, c + 2);
        }
        CP_COMMIT();

        const uint32_t Ast = sb + stage * QKV_STAGE;
        const uint32_t Bst = Ast + 16384;
#pragma unroll
        for (int ks = 0; ks < 2; ks++) {
            uint32_t ah[2][4], al[2][4];
#pragma unroll
            for (int mf = 0; mf < 2; mf++) {
                const int row = wm * 32 + mf * 16 + (lane & 15);
                const int ch = ks * 2 + (lane >> 4);
                const uint32_t rb = Ast + row * 128;
                LDSM_X4(ah[mf][0], ah[mf][1], ah[mf][2], ah[mf][3],
                        rb + (((uint32_t)(ch ^ (row & 7))) << 4));
                LDSM_X4(al[mf][0], al[mf][1], al[mf][2], al[mf][3],
                        rb + (((uint32_t)((ch + 4) ^ (row & 7))) << 4));
            }
            uint32_t bh[4][2];
#pragma unroll
            for (int gp = 0; gp < 2; gp++) {
                const int k = ks * 16 + (lane & 15);
                const int ch = wn * 4 + gp * 2 + (lane >> 4);
                const uint32_t bd = Bst + k * 128 + (((uint32_t)(ch ^ (k & 7))) << 4);
                LDSM_X4_T(bh[2 * gp][0], bh[2 * gp][1], bh[2 * gp + 1][0], bh[2 * gp + 1][1], bd);
            }
#pragma unroll
            for (int mf = 0; mf < 2; mf++)
#pragma unroll
                for (int nf = 0; nf < 4; nf++) {
                    mma16816(acc[mf][nf][0], acc[mf][nf][1], acc[mf][nf][2], acc[mf][nf][3],
                             ah[mf][0], ah[mf][1], ah[mf][2], ah[mf][3], bh[nf][0], bh[nf][1]);
                    mma16816_hacc(res[mf][nf][0], res[mf][nf][1],
                                  al[mf][0], al[mf][1], al[mf][2], al[mf][3], bh[nf][0], bh[nf][1]);
                }
        }
        stage = (stage == 2) ? 0 : stage + 1;
    }

#pragma unroll
    for (int nf = 0; nf < 4; nf++) {
        const int dd = wn * 32 + nf * 8 + (lane & 3) * 2;
        const int col = n0 + dd;
        const float b0 = __ldg(bq + col), b1 = __ldg(bq + col + 1);
        const int hh = n0 >> 6;
#pragma unroll
        for (int mf = 0; mf < 2; mf++) {
            const __half2 r01 = *(__half2*)&res[mf][nf][0];
            const __half2 r23 = *(__half2*)&res[mf][nf][1];
            const float rf[4] = { __low2float(r01), __high2float(r01),
                                  __low2float(r23), __high2float(r23) };
#pragma unroll
            for (int rs = 0; rs < 2; rs++) {
                const int row = m0 + wm * 32 + mf * 16 + (lane >> 2) + rs * 8;
                const int bb = row >> 10, ss = row & 1023;
                const size_t idx = ((size_t)((bb * NHh + hh) * Sq + ss)) * HDd + dd;
                float2 t;
                t.x = acc[mf][nf][rs * 2 + 0] + rf[rs * 2 + 0] + b0;
                t.y = acc[mf][nf][rs * 2 + 1] + rf[rs * 2 + 1] + b1;
                *(float2*)(g_q + idx) = t;
            }
        }
    }
}

// ---------------------------------------------------------------------------
// K/V projection: CTA 128x128, warp 32x64 (mf2 x nf8), single product.
// ---------------------------------------------------------------------------
#define KV_STAGE 24576
#define KV_SMEM (3 * KV_STAGE)

__global__ __launch_bounds__(256, 2) void qkv_kv_kernel(const float* __restrict__ bk,
                                                        const float* __restrict__ bv)
{
    extern __shared__ char smraw[];
    const uint32_t sb = smem_u32(smraw);
    const int tid = threadIdx.x, lane = tid & 31, wid = tid >> 5;
    const int wm = wid >> 1, wn = wid & 1;
    const int m0 = blockIdx.y * 128, n0 = blockIdx.x * 128, z = blockIdx.z;

    const __half* WH = g_wh + (size_t)(z + 1) * Hdim * Hdim;

    float acc[2][8][4];
#pragma unroll
    for (int i = 0; i < 2; i++)
#pragma unroll
        for (int j = 0; j < 8; j++)
#pragma unroll
            for (int r = 0; r < 4; r++) acc[i][j][r] = 0.f;

    auto load_chunk = [&](int st, int c) {
        const uint32_t base = sb + st * KV_STAGE;
        for (int i = tid; i < 512; i += 256) {
            const int r = i >> 2, u = i & 3;
            const size_t src = (size_t)(m0 + r) * Hdim + c * 32 + u * 8;
            cp16(base + r * 128 + (((uint32_t)(u ^ (r & 7))) << 4), g_xh + src);
        }
        for (int i = tid; i < 512; i += 256) {
            const int p = i >> 8, k = (i >> 3) & 31, u = i & 7;
            const uint32_t off = p * 4096 + k * 128 + (((uint32_t)(u ^ (k & 7))) << 4);
            cp16(base + 16384 + off, WH + (size_t)(c * 32 + k) * Hdim + n0 + p * 64 + u * 8);
        }
    };

    load_chunk(0, 0); CP_COMMIT();
    load_chunk(1, 1); CP_COMMIT();

    int stage = 0;
    for (int c = 0; c < 32; c++) {
        CP_WAIT(1);
        __syncthreads();
        if (c + 2 < 32) {
            int st2 = stage + 2; if (st2 >= 3) st2 -= 3;
            load_chunk(st2, c + 2);
        }
        CP_COMMIT();

        const uint32_t Ast = sb + stage * KV_STAGE;
        const uint32_t Bst = Ast + 16384 + wn * 4096;
#pragma unroll
        for (int ks = 0; ks < 2; ks++) {
            uint32_t ah[2][4];
#pragma unroll
            for (int mf = 0; mf < 2; mf++) {
                const int row = wm * 32 + mf * 16 + (lane & 15);
                const int ch = ks * 2 + (lane >> 4);
                LDSM_X4(ah[mf][0], ah[mf][1], ah[mf][2], ah[mf][3],
                        Ast + row * 128 + (((uint32_t)(ch ^ (row & 7))) << 4));
            }
            uint32_t bh[8][2];
#pragma unroll
            for (int gp = 0; gp < 4; gp++) {
                const int k = ks * 16 + (lane & 15);
                const int ch = gp * 2 + (lane >> 4);
                const uint32_t bd = Bst + k * 128 + (((uint32_t)(ch ^ (k & 7))) << 4);
                LDSM_X4_T(bh[2 * gp][0], bh[2 * gp][1], bh[2 * gp + 1][0], bh[2 * gp + 1][1], bd);
            }
#pragma unroll
            for (int mf = 0; mf < 2; mf++)
#pragma unroll
                for (int nf = 0; nf < 8; nf++)
                    mma16816(acc[mf][nf][0], acc[mf][nf][1], acc[mf][nf][2], acc[mf][nf][3],
                             ah[mf][0], ah[mf][1], ah[mf][2], ah[mf][3], bh[nf][0], bh[nf][1]);
        }
        stage = (stage == 2) ? 0 : stage + 1;
    }

    const float* bias = z ? bv : bk;
#pragma unroll
    for (int nf = 0; nf < 8; nf++) {
        const int dd = nf * 8 + (lane & 3) * 2;
        const int col = n0 + wn * 64 + dd;
        const float b0 = __ldg(bias + col), b1 = __ldg(bias + col + 1);
        const int hh = (n0 >> 6) + wn;
#pragma unroll
        for (int mf = 0; mf < 2; mf++) {
#pragma unroll
            for (int rs = 0; rs < 2; rs++) {
                const int row = m0 + wm * 32 + mf * 16 + (lane >> 2) + rs * 8;
                const int bb = row >> 10, ss = row & 1023;
                const size_t idx = ((size_t)((bb * NHh + hh) * Sq + ss)) * HDd + dd;
                const float v0 = acc[mf][nf][rs * 2 + 0] + b0;
                const float v1 = acc[mf][nf][rs * 2 + 1] + b1;
                if (z == 0) {
                    float2 t; t.x = v0; t.y = v1;
                    *(float2*)(g_k + idx) = t;
                } else {
                    *(uint32_t*)(g_vh + idx) = pack_h(v0, v1);
                }
            }
        }
    }
}

// ---------------------------------------------------------------------------
// Gate via mma.sync; both q and k outputs hi-only f16 now.
// ---------------------------------------------------------------------------
#define GT_CE 8192
#define GT_Q  43008
#define GT_SM 77824
#define GT_SMEM (77824 + 1536)
#define GPITCH 68

__global__ __launch_bounds__(256) void gate_mma_kernel(
    const float* __restrict__ cef,
    const float* __restrict__ bcq, const float* __restrict__ bck,
    const float* __restrict__ wlqq, const float* __restrict__ wlkk)
{
    extern __shared__ char smraw[];
    const uint32_t sb = smem_u32(smraw);
    const int tid = threadIdx.x, lane = tid & 31, wid = tid >> 5;
    const int which = blockIdx.y;
    const int row0 = blockIdx.x * 128;

    const float* vecs = which ? g_k : g_q;
    const float* bc   = which ? bck : bcq;
    const float* wlv  = which ? wlkk : wlqq;
    __half* oh = which ? g_kh : g_qh;
    const float oscale = which ? 1.0f : 0.125f;

    float* CEp = (float*)(smraw + GT_CE);
    float* Qp  = (float*)(smraw + GT_Q);
    float* lam_s = (float*)(smraw + GT_SM);
    float* u_s   = lam_s + 128;
    float* wlv_s = u_s + 64;
    float* bc_s  = wlv_s + 64;

    if (tid < 64) {
        u_s[tid] = g_u[which][tid];
        wlv_s[tid] = wlv[tid];
        bc_s[tid] = bc[tid];
    }

    for (int i = tid; i < 512; i += 256) {
        const int row = i >> 3, ch = i & 7;
        const uint32_t dst = sb + row * 128 + (((uint32_t)(ch ^ (row & 7))) << 4);
        cp16(dst, g_wgh + which * 4096 + row * 64 + ch * 8);
    }
    for (int i = tid; i < 2048; i += 256) {
        const int r = i >> 4, j = i & 15;
        const int R = row0 + r;
        const int b_ = R >> 14, h = (R >> 10) & 15, s = R & 1023;
        cp16(sb + GT_CE + r * 272 + j * 16,
             cef + ((size_t)((b_ << 10) + s)) * Hdim + (h << 6) + j * 4);
        cp16(sb + GT_Q + r * 272 + j * 16, vecs + (size_t)R * 64 + j * 4);
    }
    CP_COMMIT();
    CP_WAIT(0);
    __syncthreads();

    if (tid < 128) {
        const float* cer = CEp + tid * GPITCH;
        const float* qr = Qp + tid * GPITCH;
        float acc = g_c[which];
#pragma unroll
        for (int j = 0; j < 16; j++) {
            float4 c4 = *(const float4*)(cer + j * 4);
            float4 q4 = *(const float4*)(qr + j * 4);
            acc = fmaf(c4.x, u_s[j * 4 + 0], acc);
            acc = fmaf(c4.y, u_s[j * 4 + 1], acc);
            acc = fmaf(c4.z, u_s[j * 4 + 2], acc);
            acc = fmaf(c4.w, u_s[j * 4 + 3], acc);
            acc = fmaf(q4.x, wlv_s[j * 4 + 0], acc);
            acc = fmaf(q4.y, wlv_s[j * 4 + 1], acc);
            acc = fmaf(q4.z, wlv_s[j * 4 + 2], acc);
            acc = fmaf(q4.w, wlv_s[j * 4 + 3], acc);
        }
        lam_s[tid] = 1.f / (1.f + __expf(-acc));
    }
    __syncthreads();

    const int ra = wid * 16 + (lane >> 2);
    const int c2 = (lane & 3) * 2;
    float acc[8][4];
#pragma unroll
    for (int ng = 0; ng < 8; ng++)
#pragma unroll
        for (int r = 0; r < 4; r++) acc[ng][r] = 0.f;

#pragma unroll
    for (int ks = 0; ks < 4; ks++) {
        const int k0 = ks * 16 + c2;
        float2 x0 = *(float2*)(CEp + ra * GPITCH + k0);
        float2 x1 = *(float2*)(CEp + (ra + 8) * GPITCH + k0);
        float2 x2 = *(float2*)(CEp + ra * GPITCH + k0 + 8);
        float2 x3 = *(float2*)(CEp + (ra + 8) * GPITCH + k0 + 8);
        uint32_t ah0, al0, ah1, al1, ah2, al2, ah3, al3;
        split_pack(x0.x, x0.y, ah0, al0);
        split_pack(x1.x, x1.y, ah1, al1);
        split_pack(x2.x, x2.y, ah2, al2);
        split_pack(x3.x, x3.y, ah3, al3);

#pragma unroll
        for (int gp = 0; gp < 4; gp++) {
            const int k = ks * 16 + (lane & 15);
            const int ch = 2 * gp + (lane >> 4);
            const uint32_t bd = sb + k * 128 + (((uint32_t)(ch ^ (k & 7))) << 4);
            uint32_t b0, b1, b2, b3;
            LDSM_X4_T(b0, b1, b2, b3, bd);
            const int g0 = 2 * gp, g1 = 2 * gp + 1;
            mma16816(acc[g0][0], acc[g0][1], acc[g0][2], acc[g0][3],
                     ah0, ah1, ah2, ah3, b0, b1);
            mma16816(acc[g0][0], acc[g0][1], acc[g0][2], acc[g0][3],
                     al0, al1, al2, al3, b0, b1);
            mma16816(acc[g1][0], acc[g1][1], acc[g1][2], acc[g1][3],
                     ah0, ah1, ah2, ah3, b2, b3);
            mma16816(acc[g1][0], acc[g1][1], acc[g1][2], acc[g1][3],
                     al0, al1, al2, al3, b2, b3);
        }
    }

    const float lam0 = lam_s[ra];
    const float lam1 = lam_s[ra + 8];
    const int R0 = row0 + ra, R1 = R0 + 8;
#pragma unroll
    for (int ng = 0; ng < 8; ng++) {
        const int col = ng * 8 + c2;
        const float bcv0 = bc_s[col], bcv1 = bc_s[col + 1];
        float2 q0 = *(float2*)(Qp + ra * GPITCH + col);
        float2 q1 = *(float2*)(Qp + (ra + 8) * GPITCH + col);
        const float o00 = ((1.f - lam0) * q0.x + lam0 * (acc[ng][0] + bcv0)) * oscale;
        const float o01 = ((1.f - lam0) * q0.y + lam0 * (acc[ng][1] + bcv1)) * oscale;
        const float o10 = ((1.f - lam1) * q1.x + lam1 * (acc[ng][2] + bcv0)) * oscale;
        const float o11 = ((1.f - lam1) * q1.y + lam1 * (acc[ng][3] + bcv1)) * oscale;
        *(uint32_t*)(oh + (size_t)R0 * 64 + col) = pack_h(o00, o01);
        *(uint32_t*)(oh + (size_t)R1 * 64 + col) = pack_h(o10, o11);
    }
}

// ---------------------------------------------------------------------------
// Flash attention: single-product QK^T (Qh·K) and PV (Ph·V). All hi-only.
// SMEM: Q @0 (16K, becomes slot 2), slot0 @16K, slot1 @32K. 48KB, 2 CTA/SM.
// ---------------------------------------------------------------------------
#define ATT_SMEM 49152

__global__ __launch_bounds__(256, 2) void attn_mma_kernel(
    const float* __restrict__ amask, float* __restrict__ out)
{
    extern __shared__ char smraw[];
    const uint32_t sb = smem_u32(smraw);
    const int tid = threadIdx.x, lane = tid & 31, wid = tid >> 5;
    const int b_ = blockIdx.z, h = blockIdx.y, qt = blockIdx.x;

    const size_t bh_base = (size_t)(b_ * NHh + h) * Sq * HDd;
    const size_t qbase = bh_base + (size_t)qt * 128 * HDd;
    const float* mrow_b = amask + (size_t)b_ * Sq;

    auto slot_base = [&](int i) -> uint32_t {
        return (i == 2) ? sb : sb + 16384 + (uint32_t)i * 16384;
    };

    auto load_q = [&]() {
        for (int i = tid; i < 1024; i += 256) {
            const int row = i >> 3, ch = i & 7;
            const uint32_t dst = sb + row * 128 + (((uint32_t)(ch ^ (row & 7))) << 4);
            cp16(dst, g_qh + qbase + (size_t)row * 64 + ch * 8);
        }
    };
    auto load_kv = [&](uint32_t base, int kt) {
        for (int i = tid; i < 512; i += 256) {
            const int row = i >> 3, ch = i & 7;
            const uint32_t off = row * 128 + (((uint32_t)(ch ^ (row & 7))) << 4);
            const size_t src = bh_base + (size_t)(kt * 64 + row) * 64 + ch * 8;
            cp16(base + off, g_kh + src);
            cp16(base + 8192 + off, g_vh + src);
        }
    };

    load_q(); load_kv(slot_base(0), 0); CP_COMMIT();
    load_kv(slot_base(1), 1); CP_COMMIT();

    uint32_t qh[4][4];
    float o[8][4];
#pragma unroll
    for (int ng = 0; ng < 8; ng++)
#pragma unroll
        for (int r = 0; r < 4; r++) o[ng][r] = 0.f;
    float m0 = -1e30f, m1 = -1e30f, l0 = 0.f, l1 = 0.f;

    int slot = 0;
    for (int kt = 0; kt < 16; kt++) {
        CP_WAIT(1);
        __syncthreads();

        if (kt == 0) {
#pragma unroll
            for (int ks = 0; ks < 4; ks++) {
                const int row = wid * 16 + (lane & 15);
                const int ch = ks * 2 + (lane >> 4);
                const uint32_t ad = sb + row * 128 + (((uint32_t)(ch ^ (row & 7))) << 4);
                LDSM_X4(qh[ks][0], qh[ks][1], qh[ks][2], qh[ks][3], ad);
            }
            __syncthreads();
        }

        if (kt + 2 < 16) {
            int s2 = slot + 2; if (s2 >= 3) s2 -= 3;
            load_kv(slot_base(s2), kt + 2);
        }
        CP_COMMIT();

        const uint32_t Kst = slot_base(slot);
        const uint32_t Vst = Kst + 8192;

        float sv[8][4];
#pragma unroll
        for (int ng = 0; ng < 8; ng++)
#pragma unroll
            for (int r = 0; r < 4; r++) sv[ng][r] = 0.f;

#pragma unroll
        for (int ks = 0; ks < 4; ks++) {
#pragma unroll
            for (int gp = 0; gp < 4; gp++) {
                const int n = gp * 16 + (lane & 7) + 8 * ((lane >> 3) & 1);
                const int ch = ks * 2 + (lane >> 4);
                const uint32_t kd = Kst + n * 128 + (((uint32_t)(ch ^ (n & 7))) << 4);
                uint32_t k0, k1, k2, k3;
                LDSM_X4(k0, k1, k2, k3, kd);
                const int g0 = 2 * gp, g1 = 2 * gp + 1;
                mma16816(sv[g0][0], sv[g0][1], sv[g0][2], sv[g0][3],
                         qh[ks][0], qh[ks][1], qh[ks][2], qh[ks][3], k0, k2);
                mma16816(sv[g1][0], sv[g1][1], sv[g1][2], sv[g1][3],
                         qh[ks][0], qh[ks][1], qh[ks][2], qh[ks][3], k1, k3);
            }
        }

        const float* mrow = mrow_b + kt * 64;
        float rmx0 = -1e30f, rmx1 = -1e30f;
#pragma unroll
        for (int ng = 0; ng < 8; ng++) {
            const float mk0 = __ldg(mrow + ng * 8 + (lane & 3) * 2);
            const float mk1 = __ldg(mrow + ng * 8 + (lane & 3) * 2 + 1);
            sv[ng][0] += mk0; sv[ng][1] += mk1;
            sv[ng][2] += mk0; sv[ng][3] += mk1;
            rmx0 = fmaxf(rmx0, fmaxf(sv[ng][0], sv[ng][1]));
            rmx1 = fmaxf(rmx1, fmaxf(sv[ng][2], sv[ng][3]));
        }
        rmx0 = fmaxf(rmx0, __shfl_xor_sync(0xffffffffu, rmx0, 1));
        rmx0 = fmaxf(rmx0, __shfl_xor_sync(0xffffffffu, rmx0, 2));
        rmx1 = fmaxf(rmx1, __shfl_xor_sync(0xffffffffu, rmx1, 1));
        rmx1 = fmaxf(rmx1, __shfl_xor_sync(0xffffffffu, rmx1, 2));

        const float mn0 = fmaxf(m0, rmx0), mn1 = fmaxf(m1, rmx1);
        const float sc0 = __expf(m0 - mn0), sc1 = __expf(m1 - mn1);
        float rs0 = 0.f, rs1 = 0.f;
#pragma unroll
        for (int ng = 0; ng < 8; ng++) {
            sv[ng][0] = __expf(sv[ng][0] - mn0); rs0 += sv[ng][0];
            sv[ng][1] = __expf(sv[ng][1] - mn0); rs0 += sv[ng][1];
            sv[ng][2] = __expf(sv[ng][2] - mn1); rs1 += sv[ng][2];
            sv[ng][3] = __expf(sv[ng][3] - mn1); rs1 += sv[ng][3];
            o[ng][0] *= sc0; o[ng][1] *= sc0;
            o[ng][2] *= sc1; o[ng][3] *= sc1;
        }
        rs0 += __shfl_xor_sync(0xffffffffu, rs0, 1);
        rs0 += __shfl_xor_sync(0xffffffffu, rs0, 2);
        rs1 += __shfl_xor_sync(0xffffffffu, rs1, 1);
        rs1 += __shfl_xor_sync(0xffffffffu, rs1, 2);
        l0 = l0 * sc0 + rs0; l1 = l1 * sc1 + rs1;
        m0 = mn0; m1 = mn1;

#pragma unroll
        for (int ks = 0; ks < 4; ks++) {
            uint32_t ph[4];
            ph[0] = pack_h(sv[2 * ks][0], sv[2 * ks][1]);
            ph[1] = pack_h(sv[2 * ks][2], sv[2 * ks][3]);
            ph[2] = pack_h(sv[2 * ks + 1][0], sv[2 * ks + 1][1]);
            ph[3] = pack_h(sv[2 * ks + 1][2], sv[2 * ks + 1][3]);
#pragma unroll
            for (int gp = 0; gp < 4; gp++) {
                const int krow = ks * 16 + (lane & 15);
                const int ch = gp * 2 + (lane >> 4);
                const uint32_t vd = Vst + krow * 128 + (((uint32_t)(ch ^ (krow & 7))) << 4);
                uint32_t v0, v1, v2, v3;
                LDSM_X4_T(v0, v1, v2, v3, vd);
                const int g0 = 2 * gp, g1 = 2 * gp + 1;
                mma16816(o[g0][0], o[g0][1], o[g0][2], o[g0][3],
                         ph[0], ph[1], ph[2], ph[3], v0, v1);
                mma16816(o[g1][0], o[g1][1], o[g1][2], o[g1][3],
                         ph[0], ph[1], ph[2], ph[3], v2, v3);
            }
        }

        slot = (slot == 2) ? 0 : slot + 1;
    }

    const float inv0 = 1.f / l0, inv1 = 1.f / l1;
    const int r0 = qt * 128 + wid * 16 + (lane >> 2);
#pragma unroll
    for (int ng = 0; ng < 8; ng++) {
        const int col = h * 64 + ng * 8 + (lane & 3) * 2;
        float2 t0, t1;
        t0.x = o[ng][0] * inv0; t0.y = o[ng][1] * inv0;
        t1.x = o[ng][2] * inv1; t1.y = o[ng][3] * inv1;
        *(float2*)&out[(size_t)(b_ * Sq + r0) * Hdim + col] = t0;
        *(float2*)&out[(size_t)(b_ * Sq + r0 + 8) * Hdim + col] = t1;
    }
}

// ---------------------------------------------------------------------------
extern "C" void kernel_launch(void* const* d_in, const int* in_sizes, int n_in,
                              void* d_out, int out_size)
{
    const float* hs   = (const float*)d_in[0];
    const float* am   = (const float*)d_in[1];
    const float* ce   = (const float*)d_in[2];
    const float* Wq   = (const float*)d_in[3];
    const float* bq   = (const float*)d_in[4];
    const float* Wk   = (const float*)d_in[5];
    const float* bk   = (const float*)d_in[6];
    const float* Wv   = (const float*)d_in[7];
    const float* bv   = (const float*)d_in[8];
    const float* Wcq  = (const float*)d_in[9];
    const float* bcq  = (const float*)d_in[10];
    const float* Wck  = (const float*)d_in[11];
    const float* bck  = (const float*)d_in[12];
    const float* wlqc = (const float*)d_in[13];
    const float* wlqq = (const float*)d_in[14];
    const float* wlkc = (const float*)d_in[15];
    const float* wlkk = (const float*)d_in[16];
    float* out = (float*)d_out;
    (void)in_sizes; (void)n_in; (void)out_size;

    convert_x_kernel<<<(Bsz * Sq * Hdim / 4) / 256, 256>>>(hs);
    convert_w_kernel<<<dim3((Hdim * Hdim / 4) / 256, 3), 256>>>(Wq, Wk, Wv);
    gate_prep_kernel<<<2, 256>>>(Wcq, bcq, Wck, bck, wlqc, wlkc);

    cudaFuncSetAttribute(qkv_q_kernel, cudaFuncAttributeMaxDynamicSharedMemorySize, QKV_SMEM);
    qkv_q_kernel<<<dim3(16, 64), 256, QKV_SMEM>>>(bq);

    cudaFuncSetAttribute(qkv_kv_kernel, cudaFuncAttributeMaxDynamicSharedMemorySize, KV_SMEM);
    qkv_kv_kernel<<<dim3(8, 64, 2), 256, KV_SMEM>>>(bk, bv);

    cudaFuncSetAttribute(gate_mma_kernel, cudaFuncAttributeMaxDynamicSharedMemorySize, GT_SMEM);
    gate_mma_kernel<<<dim3(1024, 2), 256, GT_SMEM>>>(ce, bcq, bck, wlqq, wlkk);

    cudaFuncSetAttribute(attn_mma_kernel, cudaFuncAttributeMaxDynamicSharedMemorySize, ATT_SMEM);
    attn_mma_kernel<<<dim3(8, 16, 8), 256, ATT_SMEM>>>(am, out);
}